// round 8
// baseline (speedup 1.0000x reference)
#include <cuda_runtime.h>

#define NN 50000
#define NE 800000
#define HID 128
#define H4  32
#define SLOPE 0.2f
#define FULL 0xffffffffu
#define GEMM_BLOCKS 1563   // ceil((NN/4 warps * 32)/256)
#define HIST_BLOCKS 3125   // ceil(NE/256)

// ---------------- scratch ----------------
__device__ float g_xp[NN * HID];     // GEMM output (xp / z)
__device__ float g_cur[NN * HID];    // current activation
__device__ float g_ssrc[NN];
__device__ float g_sdst[NN];
__device__ float g_dinv[NN];
__device__ int   g_cnt[NN];
__device__ int   g_rowptr[NN + 1];
__device__ int   g_cursor[NN];
__device__ int   g_csrc[NE];         // CSR-sorted source ids
__device__ float g_cw[NE];           // CSR weights -> (after gcn l0) coefficients
__device__ float g_esc[NE];          // GAT edge scores (pass1 -> pass2 cache)

// ---------------- f32x2 helpers ----------------
__device__ __forceinline__ unsigned long long pk2(float a) {
    unsigned long long r;
    asm("mov.b64 %0, {%1,%1};" : "=l"(r) : "f"(a));
    return r;
}
__device__ __forceinline__ void fma2(unsigned long long& d,
                                     unsigned long long a,
                                     unsigned long long b) {
    asm("fma.rn.f32x2 %0, %1, %2, %0;" : "+l"(d) : "l"(a), "l"(b));
}
union U2 { unsigned long long u; float2 f; };

// ================= GEMM body (R7 verbatim) =============
template <bool GAT>
__device__ __forceinline__ void gemm_body(
    int gw, int lane,
    const float* __restrict__ A, const float* __restrict__ W,
    const float* __restrict__ a_src, const float* __restrict__ a_dst) {
    int r0 = gw * 4;
    if (r0 >= NN) return;
    const float4* A4 = reinterpret_cast<const float4*>(A);
    const ulonglong2* W2 = reinterpret_cast<const ulonglong2*>(W);

    unsigned long long accA[4] = {0ull, 0ull, 0ull, 0ull};
    unsigned long long accB[4] = {0ull, 0ull, 0ull, 0ull};

#pragma unroll 4
    for (int k4 = 0; k4 < 32; k4++) {
        float4 a0 = __ldg(A4 + (r0 + 0) * H4 + k4);
        float4 a1 = __ldg(A4 + (r0 + 1) * H4 + k4);
        float4 a2 = __ldg(A4 + (r0 + 2) * H4 + k4);
        float4 a3 = __ldg(A4 + (r0 + 3) * H4 + k4);
#define STEP(J, C)                                                  \
        {                                                           \
            ulonglong2 b = __ldg(W2 + (k4 * 4 + J) * H4 + lane);    \
            unsigned long long t;                                   \
            t = pk2(a0.C); fma2(accA[0], t, b.x); fma2(accB[0], t, b.y); \
            t = pk2(a1.C); fma2(accA[1], t, b.x); fma2(accB[1], t, b.y); \
            t = pk2(a2.C); fma2(accA[2], t, b.x); fma2(accB[2], t, b.y); \
            t = pk2(a3.C); fma2(accA[3], t, b.x); fma2(accB[3], t, b.y); \
        }
        STEP(0, x) STEP(1, y) STEP(2, z) STEP(3, w)
#undef STEP
    }

    float4 as, ad;
    if (GAT) {
        as = __ldg(reinterpret_cast<const float4*>(a_src) + lane);
        ad = __ldg(reinterpret_cast<const float4*>(a_dst) + lane);
    }
#pragma unroll
    for (int i = 0; i < 4; i++) {
        U2 ua, ub;
        ua.u = accA[i]; ub.u = accB[i];
        float4 o = make_float4(ua.f.x, ua.f.y, ub.f.x, ub.f.y);
        reinterpret_cast<float4*>(g_xp)[(r0 + i) * H4 + lane] = o;
        if (GAT) {
            float ps = o.x * as.x + o.y * as.y + o.z * as.z + o.w * as.w;
            float pd = o.x * ad.x + o.y * ad.y + o.z * ad.z + o.w * ad.w;
            for (int of = 16; of; of >>= 1) {
                ps += __shfl_xor_sync(FULL, ps, of);
                pd += __shfl_xor_sync(FULL, pd, of);
            }
            if (lane == 0) {
                g_ssrc[r0 + i] = ps;
                g_sdst[r0 + i] = pd;
            }
        }
    }
}

// ================= CSR build =================
__global__ void k_zero() {
    int i = blockIdx.x * blockDim.x + threadIdx.x;
    if (i < NN) g_cnt[i] = 0;
}

// Fused: blocks [0,GEMM_BLOCKS) run GAT GEMM; the rest run the degree histogram.
__global__ void k_gemm_hist(const float* __restrict__ x, const float* __restrict__ W,
                            const float* __restrict__ a_src, const float* __restrict__ a_dst,
                            const int* __restrict__ ei) {
    if (blockIdx.x < GEMM_BLOCKS) {
        int gw = (blockIdx.x * blockDim.x + threadIdx.x) >> 5;
        int lane = threadIdx.x & 31;
        gemm_body<true>(gw, lane, x, W, a_src, a_dst);
    } else {
        int e = (blockIdx.x - GEMM_BLOCKS) * blockDim.x + threadIdx.x;
        if (e < NE) atomicAdd(&g_cnt[ei[NE + e]], 1);
    }
}

#define SCAN_T 1024
__global__ void k_scan() {
    __shared__ int sh[SCAN_T];
    int t = threadIdx.x;
    const int chunk = (NN + SCAN_T - 1) / SCAN_T;
    int beg = t * chunk, end = min(beg + chunk, NN);
    int s = 0;
    for (int i = beg; i < end; i++) s += g_cnt[i];
    sh[t] = s;
    __syncthreads();
    for (int o = 1; o < SCAN_T; o <<= 1) {
        int v = (t >= o) ? sh[t - o] : 0;
        __syncthreads();
        sh[t] += v;
        __syncthreads();
    }
    int run = (t == 0) ? 0 : sh[t - 1];
    for (int i = beg; i < end; i++) {
        int c = g_cnt[i];
        g_rowptr[i] = run;
        g_cursor[i] = run;
        run += c;
    }
    if (t == SCAN_T - 1) g_rowptr[NN] = run;
}
__global__ void k_place(const int* __restrict__ ei, const float* __restrict__ w) {
    int e = blockIdx.x * blockDim.x + threadIdx.x;
    if (e >= NE) return;
    int d = ei[NE + e];
    int pos = atomicAdd(&g_cursor[d], 1);
    g_csrc[pos] = ei[e];
    g_cw[pos] = w[e];
}

// ================= plain GEMM launcher (GCN layers) =================
__global__ void k_gemm(const float* __restrict__ W) {
    int gw = (blockIdx.x * blockDim.x + threadIdx.x) >> 5;
    int lane = threadIdx.x & 31;
    gemm_body<false>(gw, lane, g_cur, W, nullptr, nullptr);
}

// ======== GAT gather: 2-pass softmax with score cache between passes =======
__global__ void k_gat(const float* __restrict__ b_gat, float* __restrict__ out) {
    int gw = (blockIdx.x * blockDim.x + threadIdx.x) >> 5;
    int lane = threadIdx.x & 31;
    if (gw >= NN) return;
    int off = g_rowptr[gw], end = g_rowptr[gw + 1];
    float sdst_d = g_sdst[gw];
    float el = g_ssrc[gw] + sdst_d;
    el = el > 0.f ? el : SLOPE * el;

    // pass 1: compute scores once (store to cache) + max + weighted degree
    float m = el;
    float wsum = (lane == 0) ? 1.0f : 0.0f;  // self-loop weight
    for (int e = off + lane; e < end; e += 32) {
        int s = g_csrc[e];
        float sc = g_ssrc[s] + sdst_d;
        sc = sc > 0.f ? sc : SLOPE * sc;
        g_esc[e] = sc;                       // cache for pass 2
        m = fmaxf(m, sc);
        wsum += g_cw[e];
    }
    for (int o = 16; o; o >>= 1) {
        m = fmaxf(m, __shfl_xor_sync(FULL, m, o));
        wsum += __shfl_xor_sync(FULL, wsum, o);
    }
    if (lane == 0) g_dinv[gw] = rsqrtf(wsum);

    // pass 2: exp (from cached score) + weighted aggregate
    const float4* xp4 = reinterpret_cast<const float4*>(g_xp);
    float p0 = __expf(el - m);
    float4 xd = xp4[gw * H4 + lane];
    float4 acc = make_float4(p0 * xd.x, p0 * xd.y, p0 * xd.z, p0 * xd.w);
    float psum = (lane == 0) ? p0 : 0.0f;
    for (int base = off; base < end; base += 32) {
        int e = base + lane;
        float p = 0.f;
        int s = 0;
        if (e < end) {
            s = g_csrc[e];
            p = __expf(g_esc[e] - m);
        }
        psum += p;
        int cnt = min(32, end - base);
        for (int j = 0; j < cnt; j++) {
            float pj = __shfl_sync(FULL, p, j);
            int sj = __shfl_sync(FULL, s, j);
            float4 xs = xp4[sj * H4 + lane];
            acc.x += pj * xs.x; acc.y += pj * xs.y;
            acc.z += pj * xs.z; acc.w += pj * xs.w;
        }
    }
    for (int o = 16; o; o >>= 1) psum += __shfl_xor_sync(FULL, psum, o);
    float inv = 1.0f / psum;
    float4 b = __ldg(reinterpret_cast<const float4*>(b_gat) + lane);
    float4 h = make_float4(acc.x * inv + b.x, acc.y * inv + b.y,
                           acc.z * inv + b.z, acc.w * inv + b.w);
    reinterpret_cast<float4*>(g_cur)[gw * H4 + lane] = h;
    reinterpret_cast<float4*>(out)[gw * H4 + lane] = h;
}

// ====== GCN gather. Layer 0 computes & stores coefficients; later layers
// ====== read them directly (each edge owned by exactly one warp -> no race).
template <bool FIRST>
__global__ void k_gcn(const float* __restrict__ b_gcn, float* __restrict__ out) {
    int gw = (blockIdx.x * blockDim.x + threadIdx.x) >> 5;
    int lane = threadIdx.x & 31;
    if (gw >= NN) return;
    int off = g_rowptr[gw], end = g_rowptr[gw + 1];
    float dv = g_dinv[gw];
    const float4* z4 = reinterpret_cast<const float4*>(g_xp);
    float cs = dv * dv;
    float4 zd = z4[gw * H4 + lane];
    float4 acc = make_float4(cs * zd.x, cs * zd.y, cs * zd.z, cs * zd.w);
    for (int base = off; base < end; base += 32) {
        int e = base + lane;
        float c = 0.f;
        int s = 0;
        if (e < end) {
            s = g_csrc[e];
            if (FIRST) {
                c = g_dinv[s] * g_cw[e] * dv;
                g_cw[e] = c;                 // materialize coefficient
            } else {
                c = g_cw[e];
            }
        }
        int cnt = min(32, end - base);
        for (int j = 0; j < cnt; j++) {
            float cj = __shfl_sync(FULL, c, j);
            int sj = __shfl_sync(FULL, s, j);
            float4 zs = z4[sj * H4 + lane];
            acc.x += cj * zs.x; acc.y += cj * zs.y;
            acc.z += cj * zs.z; acc.w += cj * zs.w;
        }
    }
    float4 b = __ldg(reinterpret_cast<const float4*>(b_gcn) + lane);
    float4 z = make_float4(fmaxf(acc.x + b.x, 0.f), fmaxf(acc.y + b.y, 0.f),
                           fmaxf(acc.z + b.z, 0.f), fmaxf(acc.w + b.w, 0.f));
    reinterpret_cast<float4*>(g_cur)[gw * H4 + lane] = z;
    float4* o4 = reinterpret_cast<float4*>(out) + gw * H4 + lane;
    float4 o = *o4;
    o.x = fmaxf(o.x, z.x); o.y = fmaxf(o.y, z.y);
    o.z = fmaxf(o.z, z.z); o.w = fmaxf(o.w, z.w);
    *o4 = o;
}

extern "C" void kernel_launch(void* const* d_in, const int* in_sizes, int n_in,
                              void* d_out, int out_size) {
    const float* x     = (const float*)d_in[0];
    const int*   ei    = (const int*)  d_in[1];
    const float* emask = (const float*)d_in[2];
    const float* W_gat = (const float*)d_in[3];
    const float* a_src = (const float*)d_in[4];
    const float* a_dst = (const float*)d_in[5];
    const float* b_gat = (const float*)d_in[6];
    const float* W_gcn = (const float*)d_in[7];
    const float* b_gcn = (const float*)d_in[8];
    float* out = (float*)d_out;

    const int nodeBlk  = (NN + 255) / 256;
    const int edgeBlk  = (NE + 255) / 256;
    const int gemmBlk  = GEMM_BLOCKS;
    const int nwarpBlk = (NN * 32 + 255) / 256;

    // CSR build overlapped with GAT GEMM
    k_zero<<<nodeBlk, 256>>>();
    k_gemm_hist<<<GEMM_BLOCKS + HIST_BLOCKS, 256>>>(x, W_gat, a_src, a_dst, ei);
    k_scan<<<1, SCAN_T>>>();
    k_place<<<edgeBlk, 256>>>(ei, emask);

    // GAT aggregate
    k_gat<<<nwarpBlk, 256>>>(b_gat, out);

    // 3x GCN + JK max
    k_gemm<<<gemmBlk, 256>>>(W_gcn + 0 * HID * HID);
    k_gcn<true><<<nwarpBlk, 256>>>(b_gcn + 0 * HID, out);
    k_gemm<<<gemmBlk, 256>>>(W_gcn + 1 * HID * HID);
    k_gcn<false><<<nwarpBlk, 256>>>(b_gcn + 1 * HID, out);
    k_gemm<<<gemmBlk, 256>>>(W_gcn + 2 * HID * HID);
    k_gcn<false><<<nwarpBlk, 256>>>(b_gcn + 2 * HID, out);
}

// round 9
// speedup vs baseline: 1.0040x; 1.0040x over previous
#include <cuda_runtime.h>

#define NN 50000
#define NE 800000
#define HID 128
#define H4  32
#define SLOPE 0.2f
#define FULL 0xffffffffu
#define GEMM_BLOCKS 1563   // ceil((NN/4 warps * 32)/256)
#define HIST_BLOCKS 3125   // ceil(NE/256)

// ---------------- scratch ----------------
__device__ float g_xp[NN * HID];     // GEMM output (xp / z)
__device__ float g_cur[NN * HID];    // current activation
__device__ float g_ssrc[NN];
__device__ float g_sdst[NN];
__device__ float g_dinv[NN];
__device__ int   g_cnt[NN];
__device__ int   g_rowptr[NN + 1];
__device__ int   g_cursor[NN];
__device__ int   g_csrc[NE];         // CSR-sorted source ids
__device__ float g_cw[NE];           // CSR weights -> (after gcn l0) coefficients

// ---------------- f32x2 helpers ----------------
__device__ __forceinline__ unsigned long long pk2(float a) {
    unsigned long long r;
    asm("mov.b64 %0, {%1,%1};" : "=l"(r) : "f"(a));
    return r;
}
__device__ __forceinline__ void fma2(unsigned long long& d,
                                     unsigned long long a,
                                     unsigned long long b) {
    asm("fma.rn.f32x2 %0, %1, %2, %0;" : "+l"(d) : "l"(a), "l"(b));
}
union U2 { unsigned long long u; float2 f; };

// ================= GEMM body (R7 verbatim) =============
template <bool GAT>
__device__ __forceinline__ void gemm_body(
    int gw, int lane,
    const float* __restrict__ A, const float* __restrict__ W,
    const float* __restrict__ a_src, const float* __restrict__ a_dst) {
    int r0 = gw * 4;
    if (r0 >= NN) return;
    const float4* A4 = reinterpret_cast<const float4*>(A);
    const ulonglong2* W2 = reinterpret_cast<const ulonglong2*>(W);

    unsigned long long accA[4] = {0ull, 0ull, 0ull, 0ull};
    unsigned long long accB[4] = {0ull, 0ull, 0ull, 0ull};

#pragma unroll 4
    for (int k4 = 0; k4 < 32; k4++) {
        float4 a0 = __ldg(A4 + (r0 + 0) * H4 + k4);
        float4 a1 = __ldg(A4 + (r0 + 1) * H4 + k4);
        float4 a2 = __ldg(A4 + (r0 + 2) * H4 + k4);
        float4 a3 = __ldg(A4 + (r0 + 3) * H4 + k4);
#define STEP(J, C)                                                  \
        {                                                           \
            ulonglong2 b = __ldg(W2 + (k4 * 4 + J) * H4 + lane);    \
            unsigned long long t;                                   \
            t = pk2(a0.C); fma2(accA[0], t, b.x); fma2(accB[0], t, b.y); \
            t = pk2(a1.C); fma2(accA[1], t, b.x); fma2(accB[1], t, b.y); \
            t = pk2(a2.C); fma2(accA[2], t, b.x); fma2(accB[2], t, b.y); \
            t = pk2(a3.C); fma2(accA[3], t, b.x); fma2(accB[3], t, b.y); \
        }
        STEP(0, x) STEP(1, y) STEP(2, z) STEP(3, w)
#undef STEP
    }

    float4 as, ad;
    if (GAT) {
        as = __ldg(reinterpret_cast<const float4*>(a_src) + lane);
        ad = __ldg(reinterpret_cast<const float4*>(a_dst) + lane);
    }
#pragma unroll
    for (int i = 0; i < 4; i++) {
        U2 ua, ub;
        ua.u = accA[i]; ub.u = accB[i];
        float4 o = make_float4(ua.f.x, ua.f.y, ub.f.x, ub.f.y);
        reinterpret_cast<float4*>(g_xp)[(r0 + i) * H4 + lane] = o;
        if (GAT) {
            float ps = o.x * as.x + o.y * as.y + o.z * as.z + o.w * as.w;
            float pd = o.x * ad.x + o.y * ad.y + o.z * ad.z + o.w * ad.w;
            for (int of = 16; of; of >>= 1) {
                ps += __shfl_xor_sync(FULL, ps, of);
                pd += __shfl_xor_sync(FULL, pd, of);
            }
            if (lane == 0) {
                g_ssrc[r0 + i] = ps;
                g_sdst[r0 + i] = pd;
            }
        }
    }
}

// ================= CSR build =================
__global__ void k_zero() {
    int i = blockIdx.x * blockDim.x + threadIdx.x;
    if (i < NN) g_cnt[i] = 0;
}

// Fused: blocks [0,GEMM_BLOCKS) run GAT GEMM; the rest run the degree histogram.
__global__ void k_gemm_hist(const float* __restrict__ x, const float* __restrict__ W,
                            const float* __restrict__ a_src, const float* __restrict__ a_dst,
                            const int* __restrict__ ei) {
    if (blockIdx.x < GEMM_BLOCKS) {
        int gw = (blockIdx.x * blockDim.x + threadIdx.x) >> 5;
        int lane = threadIdx.x & 31;
        gemm_body<true>(gw, lane, x, W, a_src, a_dst);
    } else {
        int e = (blockIdx.x - GEMM_BLOCKS) * blockDim.x + threadIdx.x;
        if (e < NE) atomicAdd(&g_cnt[ei[NE + e]], 1);
    }
}

#define SCAN_T 1024
__global__ void k_scan() {
    __shared__ int sh[SCAN_T];
    int t = threadIdx.x;
    const int chunk = (NN + SCAN_T - 1) / SCAN_T;
    int beg = t * chunk, end = min(beg + chunk, NN);
    int s = 0;
    for (int i = beg; i < end; i++) s += g_cnt[i];
    sh[t] = s;
    __syncthreads();
    for (int o = 1; o < SCAN_T; o <<= 1) {
        int v = (t >= o) ? sh[t - o] : 0;
        __syncthreads();
        sh[t] += v;
        __syncthreads();
    }
    int run = (t == 0) ? 0 : sh[t - 1];
    for (int i = beg; i < end; i++) {
        int c = g_cnt[i];
        g_rowptr[i] = run;
        g_cursor[i] = run;
        run += c;
    }
    if (t == SCAN_T - 1) g_rowptr[NN] = run;
}
__global__ void k_place(const int* __restrict__ ei, const float* __restrict__ w) {
    int e = blockIdx.x * blockDim.x + threadIdx.x;
    if (e >= NE) return;
    int d = ei[NE + e];
    int pos = atomicAdd(&g_cursor[d], 1);
    g_csrc[pos] = ei[e];
    g_cw[pos] = w[e];
}

// ================= plain GEMM launcher (GCN layers) =================
__global__ void k_gemm(const float* __restrict__ W) {
    int gw = (blockIdx.x * blockDim.x + threadIdx.x) >> 5;
    int lane = threadIdx.x & 31;
    gemm_body<false>(gw, lane, g_cur, W, nullptr, nullptr);
}

// ========= GAT gather: SINGLE pass (softmax w/o max-shift; fp32-safe) ======
// One loop computes: psum (softmax denom), wsum (weighted degree, coalesced
// g_cw reads), and the shfl-broadcast weighted aggregate.
__global__ void k_gat(const float* __restrict__ b_gat, float* __restrict__ out) {
    int gw = (blockIdx.x * blockDim.x + threadIdx.x) >> 5;
    int lane = threadIdx.x & 31;
    if (gw >= NN) return;
    int off = g_rowptr[gw], end = g_rowptr[gw + 1];
    float sdst_d = g_sdst[gw];
    float el = g_ssrc[gw] + sdst_d;
    el = el > 0.f ? el : SLOPE * el;
    float p0 = __expf(el);

    const float4* xp4 = reinterpret_cast<const float4*>(g_xp);
    float4 xd = xp4[gw * H4 + lane];
    float4 acc = make_float4(p0 * xd.x, p0 * xd.y, p0 * xd.z, p0 * xd.w);
    float psum = (lane == 0) ? p0 : 0.0f;
    float wsum = (lane == 0) ? 1.0f : 0.0f;   // self-loop weight

    for (int base = off; base < end; base += 32) {
        int e = base + lane;
        float p = 0.f;
        int s = 0;
        if (e < end) {
            s = g_csrc[e];
            float sc = g_ssrc[s] + sdst_d;
            sc = sc > 0.f ? sc : SLOPE * sc;
            p = __expf(sc);
            wsum += g_cw[e];
        }
        psum += p;
        int cnt = min(32, end - base);
        for (int j = 0; j < cnt; j++) {
            float pj = __shfl_sync(FULL, p, j);
            int sj = __shfl_sync(FULL, s, j);
            float4 xs = xp4[sj * H4 + lane];
            acc.x += pj * xs.x; acc.y += pj * xs.y;
            acc.z += pj * xs.z; acc.w += pj * xs.w;
        }
    }
    for (int o = 16; o; o >>= 1) {
        psum += __shfl_xor_sync(FULL, psum, o);
        wsum += __shfl_xor_sync(FULL, wsum, o);
    }
    if (lane == 0) g_dinv[gw] = rsqrtf(wsum);

    float inv = 1.0f / psum;
    float4 b = __ldg(reinterpret_cast<const float4*>(b_gat) + lane);
    float4 h = make_float4(acc.x * inv + b.x, acc.y * inv + b.y,
                           acc.z * inv + b.z, acc.w * inv + b.w);
    reinterpret_cast<float4*>(g_cur)[gw * H4 + lane] = h;
    reinterpret_cast<float4*>(out)[gw * H4 + lane] = h;
}

// ====== GCN gather. Layer 0 computes & stores coefficients; later layers
// ====== read them directly (each edge owned by exactly one warp -> no race).
template <bool FIRST>
__global__ void k_gcn(const float* __restrict__ b_gcn, float* __restrict__ out) {
    int gw = (blockIdx.x * blockDim.x + threadIdx.x) >> 5;
    int lane = threadIdx.x & 31;
    if (gw >= NN) return;
    int off = g_rowptr[gw], end = g_rowptr[gw + 1];
    float dv = g_dinv[gw];
    const float4* z4 = reinterpret_cast<const float4*>(g_xp);
    float cs = dv * dv;
    float4 zd = z4[gw * H4 + lane];
    float4 acc = make_float4(cs * zd.x, cs * zd.y, cs * zd.z, cs * zd.w);
    for (int base = off; base < end; base += 32) {
        int e = base + lane;
        float c = 0.f;
        int s = 0;
        if (e < end) {
            s = g_csrc[e];
            if (FIRST) {
                c = g_dinv[s] * g_cw[e] * dv;
                g_cw[e] = c;                 // materialize coefficient
            } else {
                c = g_cw[e];
            }
        }
        int cnt = min(32, end - base);
        for (int j = 0; j < cnt; j++) {
            float cj = __shfl_sync(FULL, c, j);
            int sj = __shfl_sync(FULL, s, j);
            float4 zs = z4[sj * H4 + lane];
            acc.x += cj * zs.x; acc.y += cj * zs.y;
            acc.z += cj * zs.z; acc.w += cj * zs.w;
        }
    }
    float4 b = __ldg(reinterpret_cast<const float4*>(b_gcn) + lane);
    float4 z = make_float4(fmaxf(acc.x + b.x, 0.f), fmaxf(acc.y + b.y, 0.f),
                           fmaxf(acc.z + b.z, 0.f), fmaxf(acc.w + b.w, 0.f));
    reinterpret_cast<float4*>(g_cur)[gw * H4 + lane] = z;
    float4* o4 = reinterpret_cast<float4*>(out) + gw * H4 + lane;
    float4 o = *o4;
    o.x = fmaxf(o.x, z.x); o.y = fmaxf(o.y, z.y);
    o.z = fmaxf(o.z, z.z); o.w = fmaxf(o.w, z.w);
    *o4 = o;
}

extern "C" void kernel_launch(void* const* d_in, const int* in_sizes, int n_in,
                              void* d_out, int out_size) {
    const float* x     = (const float*)d_in[0];
    const int*   ei    = (const int*)  d_in[1];
    const float* emask = (const float*)d_in[2];
    const float* W_gat = (const float*)d_in[3];
    const float* a_src = (const float*)d_in[4];
    const float* a_dst = (const float*)d_in[5];
    const float* b_gat = (const float*)d_in[6];
    const float* W_gcn = (const float*)d_in[7];
    const float* b_gcn = (const float*)d_in[8];
    float* out = (float*)d_out;

    const int nodeBlk  = (NN + 255) / 256;
    const int edgeBlk  = (NE + 255) / 256;
    const int gemmBlk  = GEMM_BLOCKS;
    const int nwarpBlk = (NN * 32 + 255) / 256;

    // CSR build overlapped with GAT GEMM
    k_zero<<<nodeBlk, 256>>>();
    k_gemm_hist<<<GEMM_BLOCKS + HIST_BLOCKS, 256>>>(x, W_gat, a_src, a_dst, ei);
    k_scan<<<1, SCAN_T>>>();
    k_place<<<edgeBlk, 256>>>(ei, emask);

    // GAT aggregate (single pass)
    k_gat<<<nwarpBlk, 256>>>(b_gat, out);

    // 3x GCN + JK max
    k_gemm<<<gemmBlk, 256>>>(W_gcn + 0 * HID * HID);
    k_gcn<true><<<nwarpBlk, 256>>>(b_gcn + 0 * HID, out);
    k_gemm<<<gemmBlk, 256>>>(W_gcn + 1 * HID * HID);
    k_gcn<false><<<nwarpBlk, 256>>>(b_gcn + 1 * HID, out);
    k_gemm<<<gemmBlk, 256>>>(W_gcn + 2 * HID * HID);
    k_gcn<false><<<nwarpBlk, 256>>>(b_gcn + 2 * HID, out);
}

// round 10
// speedup vs baseline: 1.1130x; 1.1085x over previous
#include <cuda_runtime.h>
#include <cuda_fp16.h>

#define NN 50000
#define NE 800000
#define HID 128
#define H4  32
#define SLOPE 0.2f
#define FULL 0xffffffffu
#define GEMM_BLOCKS 1563   // ceil((NN/4 warps * 32)/256)
#define HIST_BLOCKS 3125   // ceil(NE/256)

// ---------------- scratch ----------------
__device__ uint2 g_xp[NN * H4];      // GEMM output in fp16 (4 halves per lane-slot)
__device__ float g_cur[NN * HID];    // current activation (fp32)
__device__ float g_ssrc[NN];
__device__ float g_sdst[NN];
__device__ float g_dinv[NN];
__device__ int   g_cnt[NN];
__device__ int   g_rowptr[NN + 1];
__device__ int   g_cursor[NN];
__device__ int   g_csrc[NE];         // CSR-sorted source ids
__device__ float g_cw[NE];           // CSR weights -> (after gcn l0) coefficients

// ---------------- f32x2 helpers ----------------
__device__ __forceinline__ unsigned long long pk2(float a) {
    unsigned long long r;
    asm("mov.b64 %0, {%1,%1};" : "=l"(r) : "f"(a));
    return r;
}
__device__ __forceinline__ void fma2(unsigned long long& d,
                                     unsigned long long a,
                                     unsigned long long b) {
    asm("fma.rn.f32x2 %0, %1, %2, %0;" : "+l"(d) : "l"(a), "l"(b));
}
union U2 { unsigned long long u; float2 f; };

// ---------------- fp16 row pack/unpack ----------------
__device__ __forceinline__ uint2 pack_h4(float4 o) {
    __half2 h0 = __floats2half2_rn(o.x, o.y);
    __half2 h1 = __floats2half2_rn(o.z, o.w);
    uint2 v;
    v.x = *reinterpret_cast<unsigned int*>(&h0);
    v.y = *reinterpret_cast<unsigned int*>(&h1);
    return v;
}
__device__ __forceinline__ float4 unpack_h4(uint2 v) {
    __half2 h0 = *reinterpret_cast<__half2*>(&v.x);
    __half2 h1 = *reinterpret_cast<__half2*>(&v.y);
    float2 f0 = __half22float2(h0);
    float2 f1 = __half22float2(h1);
    return make_float4(f0.x, f0.y, f1.x, f1.y);
}

// ================= GEMM body (R9 math; fp16 epilogue store) =============
template <bool GAT>
__device__ __forceinline__ void gemm_body(
    int gw, int lane,
    const float* __restrict__ A, const float* __restrict__ W,
    const float* __restrict__ a_src, const float* __restrict__ a_dst) {
    int r0 = gw * 4;
    if (r0 >= NN) return;
    const float4* A4 = reinterpret_cast<const float4*>(A);
    const ulonglong2* W2 = reinterpret_cast<const ulonglong2*>(W);

    unsigned long long accA[4] = {0ull, 0ull, 0ull, 0ull};
    unsigned long long accB[4] = {0ull, 0ull, 0ull, 0ull};

#pragma unroll 4
    for (int k4 = 0; k4 < 32; k4++) {
        float4 a0 = __ldg(A4 + (r0 + 0) * H4 + k4);
        float4 a1 = __ldg(A4 + (r0 + 1) * H4 + k4);
        float4 a2 = __ldg(A4 + (r0 + 2) * H4 + k4);
        float4 a3 = __ldg(A4 + (r0 + 3) * H4 + k4);
#define STEP(J, C)                                                  \
        {                                                           \
            ulonglong2 b = __ldg(W2 + (k4 * 4 + J) * H4 + lane);    \
            unsigned long long t;                                   \
            t = pk2(a0.C); fma2(accA[0], t, b.x); fma2(accB[0], t, b.y); \
            t = pk2(a1.C); fma2(accA[1], t, b.x); fma2(accB[1], t, b.y); \
            t = pk2(a2.C); fma2(accA[2], t, b.x); fma2(accB[2], t, b.y); \
            t = pk2(a3.C); fma2(accA[3], t, b.x); fma2(accB[3], t, b.y); \
        }
        STEP(0, x) STEP(1, y) STEP(2, z) STEP(3, w)
#undef STEP
    }

    float4 as, ad;
    if (GAT) {
        as = __ldg(reinterpret_cast<const float4*>(a_src) + lane);
        ad = __ldg(reinterpret_cast<const float4*>(a_dst) + lane);
    }
#pragma unroll
    for (int i = 0; i < 4; i++) {
        U2 ua, ub;
        ua.u = accA[i]; ub.u = accB[i];
        float4 o = make_float4(ua.f.x, ua.f.y, ub.f.x, ub.f.y);
        g_xp[(r0 + i) * H4 + lane] = pack_h4(o);
        if (GAT) {
            float ps = o.x * as.x + o.y * as.y + o.z * as.z + o.w * as.w;
            float pd = o.x * ad.x + o.y * ad.y + o.z * ad.z + o.w * ad.w;
            for (int of = 16; of; of >>= 1) {
                ps += __shfl_xor_sync(FULL, ps, of);
                pd += __shfl_xor_sync(FULL, pd, of);
            }
            if (lane == 0) {
                g_ssrc[r0 + i] = ps;
                g_sdst[r0 + i] = pd;
            }
        }
    }
}

// Fused: blocks [0,GEMM_BLOCKS) run GAT GEMM; the rest run the degree histogram.
__global__ void k_gemm_hist(const float* __restrict__ x, const float* __restrict__ W,
                            const float* __restrict__ a_src, const float* __restrict__ a_dst,
                            const int* __restrict__ ei) {
    if (blockIdx.x < GEMM_BLOCKS) {
        int gw = (blockIdx.x * blockDim.x + threadIdx.x) >> 5;
        int lane = threadIdx.x & 31;
        gemm_body<true>(gw, lane, x, W, a_src, a_dst);
    } else {
        int e = (blockIdx.x - GEMM_BLOCKS) * blockDim.x + threadIdx.x;
        if (e < NE) atomicAdd(&g_cnt[ei[NE + e]], 1);
    }
}

#define SCAN_T 1024
__global__ void k_scan() {
    __shared__ int sh[SCAN_T];
    int t = threadIdx.x;
    const int chunk = (NN + SCAN_T - 1) / SCAN_T;
    int beg = t * chunk, end = min(beg + chunk, NN);
    int s = 0;
    for (int i = beg; i < end; i++) s += g_cnt[i];
    sh[t] = s;
    __syncthreads();
    for (int o = 1; o < SCAN_T; o <<= 1) {
        int v = (t >= o) ? sh[t - o] : 0;
        __syncthreads();
        sh[t] += v;
        __syncthreads();
    }
    int run = (t == 0) ? 0 : sh[t - 1];
    for (int i = beg; i < end; i++) {
        int c = g_cnt[i];
        g_rowptr[i] = run;
        g_cursor[i] = run;
        run += c;
    }
    if (t == SCAN_T - 1) g_rowptr[NN] = run;
}
__global__ void k_place(const int* __restrict__ ei, const float* __restrict__ w) {
    int e = blockIdx.x * blockDim.x + threadIdx.x;
    if (e >= NE) return;
    int d = ei[NE + e];
    int pos = atomicAdd(&g_cursor[d], 1);
    g_csrc[pos] = ei[e];
    g_cw[pos] = w[e];
}

// ================= plain GEMM launcher (GCN layers) =================
__global__ void k_gemm(const float* __restrict__ W) {
    int gw = (blockIdx.x * blockDim.x + threadIdx.x) >> 5;
    int lane = threadIdx.x & 31;
    gemm_body<false>(gw, lane, g_cur, W, nullptr, nullptr);
}

// ========= GAT gather: single pass, fp16 rows (fp32 accumulate) ============
__global__ void k_gat(const float* __restrict__ b_gat, float* __restrict__ out) {
    int gw = (blockIdx.x * blockDim.x + threadIdx.x) >> 5;
    int lane = threadIdx.x & 31;
    if (gw >= NN) return;
    int off = g_rowptr[gw], end = g_rowptr[gw + 1];
    float sdst_d = g_sdst[gw];
    float el = g_ssrc[gw] + sdst_d;
    el = el > 0.f ? el : SLOPE * el;
    float p0 = __expf(el);

    float4 xd = unpack_h4(g_xp[gw * H4 + lane]);
    float4 acc = make_float4(p0 * xd.x, p0 * xd.y, p0 * xd.z, p0 * xd.w);
    float psum = (lane == 0) ? p0 : 0.0f;
    float wsum = (lane == 0) ? 1.0f : 0.0f;   // self-loop weight

    for (int base = off; base < end; base += 32) {
        int e = base + lane;
        float p = 0.f;
        int s = 0;
        if (e < end) {
            s = g_csrc[e];
            float sc = g_ssrc[s] + sdst_d;
            sc = sc > 0.f ? sc : SLOPE * sc;
            p = __expf(sc);
            wsum += g_cw[e];
        }
        psum += p;
        int cnt = min(32, end - base);
        for (int j = 0; j < cnt; j++) {
            float pj = __shfl_sync(FULL, p, j);
            int sj = __shfl_sync(FULL, s, j);
            float4 xs = unpack_h4(g_xp[sj * H4 + lane]);
            acc.x += pj * xs.x; acc.y += pj * xs.y;
            acc.z += pj * xs.z; acc.w += pj * xs.w;
        }
    }
    for (int o = 16; o; o >>= 1) {
        psum += __shfl_xor_sync(FULL, psum, o);
        wsum += __shfl_xor_sync(FULL, wsum, o);
    }
    if (lane == 0) g_dinv[gw] = rsqrtf(wsum);

    float inv = 1.0f / psum;
    float4 b = __ldg(reinterpret_cast<const float4*>(b_gat) + lane);
    float4 h = make_float4(acc.x * inv + b.x, acc.y * inv + b.y,
                           acc.z * inv + b.z, acc.w * inv + b.w);
    reinterpret_cast<float4*>(g_cur)[gw * H4 + lane] = h;
    reinterpret_cast<float4*>(out)[gw * H4 + lane] = h;
}

// ====== GCN gather: fp16 rows, fp32 accumulate; layer 0 materializes coeffs.
template <bool FIRST>
__global__ void k_gcn(const float* __restrict__ b_gcn, float* __restrict__ out) {
    int gw = (blockIdx.x * blockDim.x + threadIdx.x) >> 5;
    int lane = threadIdx.x & 31;
    if (gw >= NN) return;
    int off = g_rowptr[gw], end = g_rowptr[gw + 1];
    float dv = g_dinv[gw];
    float cs = dv * dv;
    float4 zd = unpack_h4(g_xp[gw * H4 + lane]);
    float4 acc = make_float4(cs * zd.x, cs * zd.y, cs * zd.z, cs * zd.w);
    for (int base = off; base < end; base += 32) {
        int e = base + lane;
        float c = 0.f;
        int s = 0;
        if (e < end) {
            s = g_csrc[e];
            if (FIRST) {
                c = g_dinv[s] * g_cw[e] * dv;
                g_cw[e] = c;                 // materialize coefficient
            } else {
                c = g_cw[e];
            }
        }
        int cnt = min(32, end - base);
        for (int j = 0; j < cnt; j++) {
            float cj = __shfl_sync(FULL, c, j);
            int sj = __shfl_sync(FULL, s, j);
            float4 zs = unpack_h4(g_xp[sj * H4 + lane]);
            acc.x += cj * zs.x; acc.y += cj * zs.y;
            acc.z += cj * zs.z; acc.w += cj * zs.w;
        }
    }
    float4 b = __ldg(reinterpret_cast<const float4*>(b_gcn) + lane);
    float4 z = make_float4(fmaxf(acc.x + b.x, 0.f), fmaxf(acc.y + b.y, 0.f),
                           fmaxf(acc.z + b.z, 0.f), fmaxf(acc.w + b.w, 0.f));
    reinterpret_cast<float4*>(g_cur)[gw * H4 + lane] = z;
    float4* o4 = reinterpret_cast<float4*>(out) + gw * H4 + lane;
    float4 o = *o4;
    o.x = fmaxf(o.x, z.x); o.y = fmaxf(o.y, z.y);
    o.z = fmaxf(o.z, z.z); o.w = fmaxf(o.w, z.w);
    *o4 = o;
}

extern "C" void kernel_launch(void* const* d_in, const int* in_sizes, int n_in,
                              void* d_out, int out_size) {
    const float* x     = (const float*)d_in[0];
    const int*   ei    = (const int*)  d_in[1];
    const float* emask = (const float*)d_in[2];
    const float* W_gat = (const float*)d_in[3];
    const float* a_src = (const float*)d_in[4];
    const float* a_dst = (const float*)d_in[5];
    const float* b_gat = (const float*)d_in[6];
    const float* W_gcn = (const float*)d_in[7];
    const float* b_gcn = (const float*)d_in[8];
    float* out = (float*)d_out;

    const int edgeBlk  = (NE + 255) / 256;
    const int gemmBlk  = GEMM_BLOCKS;
    const int nwarpBlk = (NN * 32 + 255) / 256;

    // zero histogram counters (graph-capturable async memset on a device symbol)
    void* cnt_ptr = nullptr;
    cudaGetSymbolAddress(&cnt_ptr, g_cnt);
    cudaMemsetAsync(cnt_ptr, 0, NN * sizeof(int));

    // CSR build overlapped with GAT GEMM
    k_gemm_hist<<<GEMM_BLOCKS + HIST_BLOCKS, 256>>>(x, W_gat, a_src, a_dst, ei);
    k_scan<<<1, SCAN_T>>>();
    k_place<<<edgeBlk, 256>>>(ei, emask);

    // GAT aggregate (single pass)
    k_gat<<<nwarpBlk, 256>>>(b_gat, out);

    // 3x GCN + JK max
    k_gemm<<<gemmBlk, 256>>>(W_gcn + 0 * HID * HID);
    k_gcn<true><<<nwarpBlk, 256>>>(b_gcn + 0 * HID, out);
    k_gemm<<<gemmBlk, 256>>>(W_gcn + 1 * HID * HID);
    k_gcn<false><<<nwarpBlk, 256>>>(b_gcn + 1 * HID, out);
    k_gemm<<<gemmBlk, 256>>>(W_gcn + 2 * HID * HID);
    k_gcn<false><<<nwarpBlk, 256>>>(b_gcn + 2 * HID, out);
}

// round 11
// speedup vs baseline: 1.3965x; 1.2547x over previous
#include <cuda_runtime.h>
#include <cuda_fp16.h>

#define NN 50000
#define NE 800000
#define HID 128
#define H4  32
#define SLOPE 0.2f
#define FULL 0xffffffffu
#define GEMM_BLOCKS 1563   // ceil((NN/4 warps * 32)/256)
#define HIST_BLOCKS 3125   // ceil(NE/256)
#define WTS 68             // Wt smem row stride in 32-bit words (136 halves)

// ---------------- scratch ----------------
__device__ uint2 g_xp[NN * H4];      // GEMM output, fp16 row-major [node][128]
__device__ uint2 g_curh[NN * H4];    // current activation, fp16 row-major
__device__ unsigned g_wh[3 * HID * HID / 2];  // 3x GCN W transposed fp16 [n][k]
__device__ float g_ssrc[NN];
__device__ float g_sdst[NN];
__device__ float g_dinv[NN];
__device__ int   g_cnt[NN];
__device__ int   g_rowptr[NN + 1];
__device__ int   g_cursor[NN];
__device__ int   g_csrc[NE];
__device__ float g_cw[NE];

// ---------------- f32x2 helpers ----------------
__device__ __forceinline__ unsigned long long pk2(float a) {
    unsigned long long r;
    asm("mov.b64 %0, {%1,%1};" : "=l"(r) : "f"(a));
    return r;
}
__device__ __forceinline__ void fma2(unsigned long long& d,
                                     unsigned long long a,
                                     unsigned long long b) {
    asm("fma.rn.f32x2 %0, %1, %2, %0;" : "+l"(d) : "l"(a), "l"(b));
}
union U2 { unsigned long long u; float2 f; };

// ---------------- fp16 pack/unpack ----------------
__device__ __forceinline__ uint2 pack_h4(float4 o) {
    __half2 h0 = __floats2half2_rn(o.x, o.y);
    __half2 h1 = __floats2half2_rn(o.z, o.w);
    uint2 v;
    v.x = *reinterpret_cast<unsigned int*>(&h0);
    v.y = *reinterpret_cast<unsigned int*>(&h1);
    return v;
}
__device__ __forceinline__ float4 unpack_h4(uint2 v) {
    __half2 h0 = *reinterpret_cast<__half2*>(&v.x);
    __half2 h1 = *reinterpret_cast<__half2*>(&v.y);
    float2 f0 = __half22float2(h0);
    float2 f1 = __half22float2(h1);
    return make_float4(f0.x, f0.y, f1.x, f1.y);
}

// ================= GAT GEMM body (R10 verbatim) =============
__device__ __forceinline__ void gemm_body_gat(
    int gw, int lane,
    const float* __restrict__ A, const float* __restrict__ W,
    const float* __restrict__ a_src, const float* __restrict__ a_dst) {
    int r0 = gw * 4;
    if (r0 >= NN) return;
    const float4* A4 = reinterpret_cast<const float4*>(A);
    const ulonglong2* W2 = reinterpret_cast<const ulonglong2*>(W);

    unsigned long long accA[4] = {0ull, 0ull, 0ull, 0ull};
    unsigned long long accB[4] = {0ull, 0ull, 0ull, 0ull};

#pragma unroll 4
    for (int k4 = 0; k4 < 32; k4++) {
        float4 a0 = __ldg(A4 + (r0 + 0) * H4 + k4);
        float4 a1 = __ldg(A4 + (r0 + 1) * H4 + k4);
        float4 a2 = __ldg(A4 + (r0 + 2) * H4 + k4);
        float4 a3 = __ldg(A4 + (r0 + 3) * H4 + k4);
#define STEP(J, C)                                                  \
        {                                                           \
            ulonglong2 b = __ldg(W2 + (k4 * 4 + J) * H4 + lane);    \
            unsigned long long t;                                   \
            t = pk2(a0.C); fma2(accA[0], t, b.x); fma2(accB[0], t, b.y); \
            t = pk2(a1.C); fma2(accA[1], t, b.x); fma2(accB[1], t, b.y); \
            t = pk2(a2.C); fma2(accA[2], t, b.x); fma2(accB[2], t, b.y); \
            t = pk2(a3.C); fma2(accA[3], t, b.x); fma2(accB[3], t, b.y); \
        }
        STEP(0, x) STEP(1, y) STEP(2, z) STEP(3, w)
#undef STEP
    }

    float4 as = __ldg(reinterpret_cast<const float4*>(a_src) + lane);
    float4 ad = __ldg(reinterpret_cast<const float4*>(a_dst) + lane);
#pragma unroll
    for (int i = 0; i < 4; i++) {
        U2 ua, ub;
        ua.u = accA[i]; ub.u = accB[i];
        float4 o = make_float4(ua.f.x, ua.f.y, ub.f.x, ub.f.y);
        g_xp[(r0 + i) * H4 + lane] = pack_h4(o);
        float ps = o.x * as.x + o.y * as.y + o.z * as.z + o.w * as.w;
        float pd = o.x * ad.x + o.y * ad.y + o.z * ad.z + o.w * ad.w;
        for (int of = 16; of; of >>= 1) {
            ps += __shfl_xor_sync(FULL, ps, of);
            pd += __shfl_xor_sync(FULL, pd, of);
        }
        if (lane == 0) {
            g_ssrc[r0 + i] = ps;
            g_sdst[r0 + i] = pd;
        }
    }
}

// Fused: blocks [0,GEMM_BLOCKS) run GAT GEMM; the rest run the degree histogram.
__global__ void k_gemm_hist(const float* __restrict__ x, const float* __restrict__ W,
                            const float* __restrict__ a_src, const float* __restrict__ a_dst,
                            const int* __restrict__ ei) {
    if (blockIdx.x < GEMM_BLOCKS) {
        int gw = (blockIdx.x * blockDim.x + threadIdx.x) >> 5;
        int lane = threadIdx.x & 31;
        gemm_body_gat(gw, lane, x, W, a_src, a_dst);
    } else {
        int e = (blockIdx.x - GEMM_BLOCKS) * blockDim.x + threadIdx.x;
        if (e < NE) atomicAdd(&g_cnt[ei[NE + e]], 1);
    }
}

// ============ convert 3 GCN weight matrices to transposed fp16 =============
__global__ void k_cvtW(const float* __restrict__ Wg) {
    int m = blockIdx.x;
    const float* Wm = Wg + m * HID * HID;
    __half* dst = reinterpret_cast<__half*>(g_wh) + m * HID * HID;
    for (int i = threadIdx.x; i < HID * HID; i += blockDim.x) {
        int k = i >> 7, n = i & 127;          // read coalesced over n
        dst[n * HID + k] = __float2half(Wm[i]);
    }
}

#define SCAN_T 1024
__global__ void k_scan() {
    __shared__ int sh[SCAN_T];
    int t = threadIdx.x;
    const int chunk = (NN + SCAN_T - 1) / SCAN_T;
    int beg = t * chunk, end = min(beg + chunk, NN);
    int s = 0;
    for (int i = beg; i < end; i++) s += g_cnt[i];
    sh[t] = s;
    __syncthreads();
    for (int o = 1; o < SCAN_T; o <<= 1) {
        int v = (t >= o) ? sh[t - o] : 0;
        __syncthreads();
        sh[t] += v;
        __syncthreads();
    }
    int run = (t == 0) ? 0 : sh[t - 1];
    for (int i = beg; i < end; i++) {
        int c = g_cnt[i];
        g_rowptr[i] = run;
        g_cursor[i] = run;
        run += c;
    }
    if (t == SCAN_T - 1) g_rowptr[NN] = run;
}
__global__ void k_place(const int* __restrict__ ei, const float* __restrict__ w) {
    int e = blockIdx.x * blockDim.x + threadIdx.x;
    if (e >= NE) return;
    int d = ei[NE + e];
    int pos = atomicAdd(&g_cursor[d], 1);
    g_csrc[pos] = ei[e];
    g_cw[pos] = w[e];
}

// ================= tensor-core GEMM: g_xp = g_curh @ W (fp16 in, fp32 acc) ==
// Block: 128 threads (4 warps), 64 rows. Warp: 16 rows via m16n8k16.
__global__ void __launch_bounds__(128)
k_hgemm(int mat) {
    __shared__ unsigned Wt_s[HID * WTS];     // Wt [n][k] fp16, padded rows
    const unsigned* wh = g_wh + mat * (HID * HID / 2);
    // load Wt into smem with padding
    for (int i = threadIdx.x; i < HID * 64; i += 128) {
        int n = i >> 6, kk = i & 63;
        Wt_s[n * WTS + kk] = wh[n * 64 + kk];
    }
    __syncthreads();

    int warp = threadIdx.x >> 5;
    int lane = threadIdx.x & 31;
    int g = lane >> 2, tg = lane & 3;
    int rows0 = blockIdx.x * 64 + warp * 16;
    int r0 = rows0 + g, r1 = rows0 + g + 8;
    int r0c = min(r0, NN - 1), r1c = min(r1, NN - 1);

    const unsigned* curh32 = reinterpret_cast<const unsigned*>(g_curh);
    float acc[64];
#pragma unroll
    for (int i = 0; i < 64; i++) acc[i] = 0.f;

#pragma unroll
    for (int ks = 0; ks < 8; ks++) {
        unsigned a0 = __ldg(curh32 + r0c * 64 + ks * 8 + tg);
        unsigned a1 = __ldg(curh32 + r1c * 64 + ks * 8 + tg);
        unsigned a2 = __ldg(curh32 + r0c * 64 + ks * 8 + tg + 4);
        unsigned a3 = __ldg(curh32 + r1c * 64 + ks * 8 + tg + 4);
#pragma unroll
        for (int nt = 0; nt < 16; nt++) {
            unsigned b0 = Wt_s[(nt * 8 + g) * WTS + ks * 8 + tg];
            unsigned b1 = Wt_s[(nt * 8 + g) * WTS + ks * 8 + tg + 4];
            asm volatile(
                "mma.sync.aligned.m16n8k16.row.col.f32.f16.f16.f32 "
                "{%0,%1,%2,%3}, {%4,%5,%6,%7}, {%8,%9}, {%0,%1,%2,%3};"
                : "+f"(acc[nt * 4 + 0]), "+f"(acc[nt * 4 + 1]),
                  "+f"(acc[nt * 4 + 2]), "+f"(acc[nt * 4 + 3])
                : "r"(a0), "r"(a1), "r"(a2), "r"(a3), "r"(b0), "r"(b1));
        }
    }

    unsigned* xp32 = reinterpret_cast<unsigned*>(g_xp);
#pragma unroll
    for (int nt = 0; nt < 16; nt++) {
        int col = nt * 8 + tg * 2;
        __half2 h01 = __floats2half2_rn(acc[nt * 4 + 0], acc[nt * 4 + 1]);
        __half2 h23 = __floats2half2_rn(acc[nt * 4 + 2], acc[nt * 4 + 3]);
        if (r0 < NN) xp32[r0 * 64 + col / 2] = *reinterpret_cast<unsigned*>(&h01);
        if (r1 < NN) xp32[r1 * 64 + col / 2] = *reinterpret_cast<unsigned*>(&h23);
    }
}

// ========= GAT gather: single pass, fp16 rows (fp32 accumulate) ============
__global__ void k_gat(const float* __restrict__ b_gat, float* __restrict__ out) {
    int gw = (blockIdx.x * blockDim.x + threadIdx.x) >> 5;
    int lane = threadIdx.x & 31;
    if (gw >= NN) return;
    int off = g_rowptr[gw], end = g_rowptr[gw + 1];
    float sdst_d = g_sdst[gw];
    float el = g_ssrc[gw] + sdst_d;
    el = el > 0.f ? el : SLOPE * el;
    float p0 = __expf(el);

    float4 xd = unpack_h4(g_xp[gw * H4 + lane]);
    float4 acc = make_float4(p0 * xd.x, p0 * xd.y, p0 * xd.z, p0 * xd.w);
    float psum = (lane == 0) ? p0 : 0.0f;
    float wsum = (lane == 0) ? 1.0f : 0.0f;   // self-loop weight

    for (int base = off; base < end; base += 32) {
        int e = base + lane;
        float p = 0.f;
        int s = 0;
        if (e < end) {
            s = g_csrc[e];
            float sc = g_ssrc[s] + sdst_d;
            sc = sc > 0.f ? sc : SLOPE * sc;
            p = __expf(sc);
            wsum += g_cw[e];
        }
        psum += p;
        int cnt = min(32, end - base);
        for (int j = 0; j < cnt; j++) {
            float pj = __shfl_sync(FULL, p, j);
            int sj = __shfl_sync(FULL, s, j);
            float4 xs = unpack_h4(g_xp[sj * H4 + lane]);
            acc.x += pj * xs.x; acc.y += pj * xs.y;
            acc.z += pj * xs.z; acc.w += pj * xs.w;
        }
    }
    for (int o = 16; o; o >>= 1) {
        psum += __shfl_xor_sync(FULL, psum, o);
        wsum += __shfl_xor_sync(FULL, wsum, o);
    }
    if (lane == 0) g_dinv[gw] = rsqrtf(wsum);

    float inv = 1.0f / psum;
    float4 b = __ldg(reinterpret_cast<const float4*>(b_gat) + lane);
    float4 h = make_float4(acc.x * inv + b.x, acc.y * inv + b.y,
                           acc.z * inv + b.z, acc.w * inv + b.w);
    g_curh[gw * H4 + lane] = pack_h4(h);
    reinterpret_cast<float4*>(out)[gw * H4 + lane] = h;
}

// ====== GCN gather: fp16 rows, fp32 accumulate; layer 0 materializes coeffs.
template <bool FIRST>
__global__ void k_gcn(const float* __restrict__ b_gcn, float* __restrict__ out) {
    int gw = (blockIdx.x * blockDim.x + threadIdx.x) >> 5;
    int lane = threadIdx.x & 31;
    if (gw >= NN) return;
    int off = g_rowptr[gw], end = g_rowptr[gw + 1];
    float dv = g_dinv[gw];
    float cs = dv * dv;
    float4 zd = unpack_h4(g_xp[gw * H4 + lane]);
    float4 acc = make_float4(cs * zd.x, cs * zd.y, cs * zd.z, cs * zd.w);
    for (int base = off; base < end; base += 32) {
        int e = base + lane;
        float c = 0.f;
        int s = 0;
        if (e < end) {
            s = g_csrc[e];
            if (FIRST) {
                c = g_dinv[s] * g_cw[e] * dv;
                g_cw[e] = c;
            } else {
                c = g_cw[e];
            }
        }
        int cnt = min(32, end - base);
        for (int j = 0; j < cnt; j++) {
            float cj = __shfl_sync(FULL, c, j);
            int sj = __shfl_sync(FULL, s, j);
            float4 zs = unpack_h4(g_xp[sj * H4 + lane]);
            acc.x += cj * zs.x; acc.y += cj * zs.y;
            acc.z += cj * zs.z; acc.w += cj * zs.w;
        }
    }
    float4 b = __ldg(reinterpret_cast<const float4*>(b_gcn) + lane);
    float4 z = make_float4(fmaxf(acc.x + b.x, 0.f), fmaxf(acc.y + b.y, 0.f),
                           fmaxf(acc.z + b.z, 0.f), fmaxf(acc.w + b.w, 0.f));
    g_curh[gw * H4 + lane] = pack_h4(z);
    float4* o4 = reinterpret_cast<float4*>(out) + gw * H4 + lane;
    float4 o = *o4;
    o.x = fmaxf(o.x, z.x); o.y = fmaxf(o.y, z.y);
    o.z = fmaxf(o.z, z.z); o.w = fmaxf(o.w, z.w);
    *o4 = o;
}

extern "C" void kernel_launch(void* const* d_in, const int* in_sizes, int n_in,
                              void* d_out, int out_size) {
    const float* x     = (const float*)d_in[0];
    const int*   ei    = (const int*)  d_in[1];
    const float* emask = (const float*)d_in[2];
    const float* W_gat = (const float*)d_in[3];
    const float* a_src = (const float*)d_in[4];
    const float* a_dst = (const float*)d_in[5];
    const float* b_gat = (const float*)d_in[6];
    const float* W_gcn = (const float*)d_in[7];
    const float* b_gcn = (const float*)d_in[8];
    float* out = (float*)d_out;

    const int edgeBlk  = (NE + 255) / 256;
    const int nwarpBlk = (NN * 32 + 255) / 256;
    const int hgemmBlk = (NN + 63) / 64;

    void* cnt_ptr = nullptr;
    cudaGetSymbolAddress(&cnt_ptr, g_cnt);
    cudaMemsetAsync(cnt_ptr, 0, NN * sizeof(int));

    // weight conversion + (GAT GEMM ∥ degree histogram)
    k_cvtW<<<3, 1024>>>(W_gcn);
    k_gemm_hist<<<GEMM_BLOCKS + HIST_BLOCKS, 256>>>(x, W_gat, a_src, a_dst, ei);
    k_scan<<<1, SCAN_T>>>();
    k_place<<<edgeBlk, 256>>>(ei, emask);

    // GAT aggregate
    k_gat<<<nwarpBlk, 256>>>(b_gat, out);

    // 3x GCN (tensor-core GEMM) + JK max
    k_hgemm<<<hgemmBlk, 128>>>(0);
    k_gcn<true><<<nwarpBlk, 256>>>(b_gcn + 0 * HID, out);
    k_hgemm<<<hgemmBlk, 128>>>(1);
    k_gcn<false><<<nwarpBlk, 256>>>(b_gcn + 1 * HID, out);
    k_hgemm<<<hgemmBlk, 128>>>(2);
    k_gcn<false><<<nwarpBlk, 256>>>(b_gcn + 2 * HID, out);
}